// round 16
// baseline (speedup 1.0000x reference)
#include <cuda_runtime.h>
#include <cuda_fp16.h>
#include <math.h>
#include <stdint.h>

#define DIMQ     1024
#define HEADS    16
#define DHEAD    64
#define SEQ      2048
#define BATCH    2
#define NTOK     (BATCH * SEQ)      // 4096
#define QKV_N    (3 * DIMQ)         // 3072
#define SCALE_A  0.125f             // 1/sqrt(64)
#define LOG2E    1.4426950408889634f
#define NSM      148

// Scratch (static device globals — allocation-free)
__device__ __half g_qkv[(size_t)NTOK * QKV_N];   // Q|K|V fp16
__device__ __half g_att[(size_t)NTOK * DIMQ];    // attention result fp16
__device__ __half g_xh[(size_t)NTOK * DIMQ];     // x fp16 [m][k]
__device__ __half g_wqkvT[(size_t)QKV_N * DIMQ]; // W_qkv^T fp16 [n][k]
__device__ __half g_woutT[(size_t)DIMQ * DIMQ];  // W_out^T fp16 [n][k]

// ---------------------------------------------------------------------------
// helpers
// ---------------------------------------------------------------------------
__device__ __forceinline__ uint32_t smem_u32(const void* p) {
    uint32_t a;
    asm("{ .reg .u64 t; cvta.to.shared.u64 t, %1; cvt.u32.u64 %0, t; }"
        : "=r"(a) : "l"(p));
    return a;
}
__device__ __forceinline__ void mma_f16(float* c, const uint32_t* a, const uint32_t* b) {
    asm volatile(
        "mma.sync.aligned.m16n8k16.row.col.f32.f16.f16.f32 "
        "{%0,%1,%2,%3},{%4,%5,%6,%7},{%8,%9},{%0,%1,%2,%3};"
        : "+f"(c[0]), "+f"(c[1]), "+f"(c[2]), "+f"(c[3])
        : "r"(a[0]), "r"(a[1]), "r"(a[2]), "r"(a[3]),
          "r"(b[0]), "r"(b[1]));
}
__device__ __forceinline__ void ldsm_x4(uint32_t* r, uint32_t addr) {
    asm volatile("ldmatrix.sync.aligned.m8n8.x4.shared.b16 {%0,%1,%2,%3}, [%4];"
                 : "=r"(r[0]), "=r"(r[1]), "=r"(r[2]), "=r"(r[3]) : "r"(addr));
}
__device__ __forceinline__ void ldsm_x4_t(uint32_t* r, uint32_t addr) {
    asm volatile("ldmatrix.sync.aligned.m8n8.x4.trans.shared.b16 {%0,%1,%2,%3}, [%4];"
                 : "=r"(r[0]), "=r"(r[1]), "=r"(r[2]), "=r"(r[3]) : "r"(addr));
}
__device__ __forceinline__ uint32_t packh2(float a, float b) {
    __half2 h = __floats2half2_rn(a, b);
    return *(uint32_t*)&h;
}
__device__ __forceinline__ void cp16(uint32_t dst, const void* src) {
    asm volatile("cp.async.cg.shared.global [%0], [%1], 16;"
                 :: "r"(dst), "l"(src) : "memory");
}
#define CP_COMMIT() asm volatile("cp.async.commit_group;" ::: "memory")
#define CP_WAIT(n)  asm volatile("cp.async.wait_group %0;" :: "n"(n) : "memory")

// ---------------------------------------------------------------------------
// f32 -> f16 convert (n multiple of 8)
// ---------------------------------------------------------------------------
__global__ void __launch_bounds__(256) f32_to_f16(
    const float* __restrict__ in, __half* __restrict__ out, int n)
{
    int i = (blockIdx.x * 256 + threadIdx.x) * 8;
    if (i < n) {
        float4 a = *(const float4*)(in + i);
        float4 b = *(const float4*)(in + i + 4);
        __half2 h[4];
        h[0] = __floats2half2_rn(a.x, a.y);
        h[1] = __floats2half2_rn(a.z, a.w);
        h[2] = __floats2half2_rn(b.x, b.y);
        h[3] = __floats2half2_rn(b.z, b.w);
        *(uint4*)(out + i) = *(uint4*)h;
    }
}

// f32 [R][C] -> f16 transposed [C][R]
__global__ void __launch_bounds__(256) f32_to_f16_T(
    const float* __restrict__ in, __half* __restrict__ out, int R, int C)
{
    __shared__ float t[32][33];
    int bx = blockIdx.x * 32, by = blockIdx.y * 32;
    int x = threadIdx.x, y = threadIdx.y;   // 32 x 8
    #pragma unroll
    for (int i = 0; i < 32; i += 8)
        t[y + i][x] = in[(size_t)(by + y + i) * C + bx + x];
    __syncthreads();
    #pragma unroll
    for (int i = 0; i < 32; i += 8)
        out[(size_t)(bx + y + i) * R + by + x] = __float2half(t[x][y + i]);
}

// ---------------------------------------------------------------------------
// fp16 mma.sync GEMM v5: PERSISTENT CTAs (no wave quantization) + tail-safe
// cp.async waits. C = A @ BT^T (+bias). 128x128 tile, BK=32, 4 warps (2x2),
// warp tile 64x64, 4-stage cp.async pipeline.
// ---------------------------------------------------------------------------
#define HST 40
#define NSTAGE 4
#define STG_HALVES (128 * HST)
#define GEMM_SMEM (2 * NSTAGE * STG_HALVES * 2)   // 81920 bytes

__global__ void __launch_bounds__(128, 2) gemm_f16(
    const __half* __restrict__ A, const __half* __restrict__ BT,
    const float* __restrict__ bias, void* __restrict__ Cout,
    int M, int N, int K, int out_half)
{
    extern __shared__ __half smh[];
    const uint32_t sb = smem_u32(smh);
    uint32_t as_b[NSTAGE], bs_b[NSTAGE];
    #pragma unroll
    for (int s = 0; s < NSTAGE; s++) {
        as_b[s] = sb + (uint32_t)(s * STG_HALVES) * 2;
        bs_b[s] = sb + (uint32_t)((NSTAGE + s) * STG_HALVES) * 2;
    }

    const int tid  = threadIdx.x;
    const int lane = tid & 31;
    const int wid  = tid >> 5;
    const int wm   = wid & 1;
    const int wn   = wid >> 1;

    const uint32_t sts_off = (uint32_t)(tid * HST) * 2;
    const uint32_t a_off = (uint32_t)((lane & 15) * HST + (lane >> 4) * 8) * 2;
    const uint32_t b_off = (uint32_t)(((lane & 7) + ((lane >> 4) << 3)) * HST
                                      + ((lane >> 3) & 1) * 8) * 2;
    const int lq = lane >> 2;
    const int lr = lane & 3;

    const int ntx = N / 128;
    const int ntiles = (M / 128) * ntx;
    const int NC = K / 32;

    for (int tile = blockIdx.x; tile < ntiles; tile += gridDim.x) {
        const long row0 = (long)(tile / ntx) * 128;
        const long col0 = (long)(tile % ntx) * 128;

        const __half* Ap = A  + (size_t)(row0 + tid) * K;
        const __half* Bp = BT + (size_t)(col0 + tid) * K;

        float acc[4][8][4];
        #pragma unroll
        for (int mt = 0; mt < 4; mt++)
            #pragma unroll
            for (int nt = 0; nt < 8; nt++)
                #pragma unroll
                for (int i = 0; i < 4; i++) acc[mt][nt][i] = 0.f;

        __syncthreads();   // prior tile's compute done before stage reuse

        #pragma unroll
        for (int s = 0; s < 3; s++) {
            const long kc = (long)s * 32;
            #pragma unroll
            for (int j = 0; j < 4; j++) {
                cp16(as_b[s] + sts_off + j * 16, Ap + kc + j * 8);
                cp16(bs_b[s] + sts_off + j * 16, Bp + kc + j * 8);
            }
            CP_COMMIT();
        }

        for (int c = 0; c < NC; c++) {
            const int buf = c & (NSTAGE - 1);
            // tail-safe wait: guarantee chunk c landed
            if (c <= NC - 3)      CP_WAIT(2);
            else if (c == NC - 2) CP_WAIT(1);
            else                  CP_WAIT(0);
            __syncthreads();

            if (c + 3 < NC) {
                const int nb = (c + 3) & (NSTAGE - 1);
                const long kc = (long)(c + 3) * 32;
                #pragma unroll
                for (int j = 0; j < 4; j++) {
                    cp16(as_b[nb] + sts_off + j * 16, Ap + kc + j * 8);
                    cp16(bs_b[nb] + sts_off + j * 16, Bp + kc + j * 8);
                }
                CP_COMMIT();
            }

            #pragma unroll
            for (int ks = 0; ks < 2; ks++) {
                uint32_t af[4][4];
                #pragma unroll
                for (int mt = 0; mt < 4; mt++)
                    ldsm_x4(af[mt], as_b[buf]
                            + (uint32_t)((wm * 64 + mt * 16) * HST + ks * 16) * 2
                            + a_off);
                uint32_t bf[8][2];
                #pragma unroll
                for (int bg = 0; bg < 4; bg++) {
                    uint32_t t[4];
                    ldsm_x4(t, bs_b[buf]
                            + (uint32_t)((wn * 64 + bg * 16) * HST + ks * 16) * 2
                            + b_off);
                    bf[bg * 2][0]     = t[0];
                    bf[bg * 2][1]     = t[1];
                    bf[bg * 2 + 1][0] = t[2];
                    bf[bg * 2 + 1][1] = t[3];
                }
                #pragma unroll
                for (int mt = 0; mt < 4; mt++)
                    #pragma unroll
                    for (int nt = 0; nt < 8; nt++)
                        mma_f16(acc[mt][nt], af[mt], bf[nt]);
            }
        }

        if (out_half) {
            __half* Ch = (__half*)Cout;
            #pragma unroll
            for (int mt = 0; mt < 4; mt++) {
                long r0 = row0 + wm * 64 + mt * 16 + lq;
                #pragma unroll
                for (int nt = 0; nt < 8; nt++) {
                    long c = col0 + wn * 64 + nt * 8 + 2 * lr;
                    *(__half2*)(Ch + r0 * N + c) =
                        __floats2half2_rn(acc[mt][nt][0], acc[mt][nt][1]);
                    *(__half2*)(Ch + (r0 + 8) * N + c) =
                        __floats2half2_rn(acc[mt][nt][2], acc[mt][nt][3]);
                }
            }
        } else {
            float* Cf = (float*)Cout;
            #pragma unroll
            for (int mt = 0; mt < 4; mt++) {
                long r0 = row0 + wm * 64 + mt * 16 + lq;
                #pragma unroll
                for (int nt = 0; nt < 8; nt++) {
                    long c = col0 + wn * 64 + nt * 8 + 2 * lr;
                    float bx = bias ? bias[c] : 0.f;
                    float by = bias ? bias[c + 1] : 0.f;
                    float2 v0, v1;
                    v0.x = acc[mt][nt][0] + bx; v0.y = acc[mt][nt][1] + by;
                    v1.x = acc[mt][nt][2] + bx; v1.y = acc[mt][nt][3] + by;
                    *(float2*)(Cf + r0 * N + c)       = v0;
                    *(float2*)(Cf + (r0 + 8) * N + c) = v1;
                }
            }
        }
    }
}

// ---------------------------------------------------------------------------
// fp16 flash attention v4 (R15 winner + tail-safe wait). CTA = 128 q-rows,
// 4 warps, register-direct P, 3-stage cp.async K/V pipeline.
// ---------------------------------------------------------------------------
#define FA_STG 3
#define FA_SMEM ((8192 + 6 * 4096) * 2)   // 65536 bytes

__global__ void __launch_bounds__(128, 2) flash_attn_f16(
    const __half* __restrict__ qkv, __half* __restrict__ out)
{
    extern __shared__ __half fsm[];
    const uint32_t sb = smem_u32(fsm);
    const uint32_t qp_b = sb;
    uint32_t ks_b[FA_STG], vs_b[FA_STG];
    #pragma unroll
    for (int s = 0; s < FA_STG; s++) {
        ks_b[s] = sb + (uint32_t)(8192 + s * 4096) * 2;
        vs_b[s] = sb + (uint32_t)(8192 + (3 + s) * 4096) * 2;
    }
    __half* QP = fsm;

    const int tid  = threadIdx.x;
    const int lane = tid & 31;
    const int wid  = tid >> 5;
    const int lq   = lane >> 2;
    const int lr   = lane & 3;
    const int wr   = wid * 32;

    const int h  = blockIdx.y;
    const int b  = blockIdx.z;
    const int q0 = blockIdx.x * 128;

    const size_t base = (size_t)b * SEQ * QKV_N;
    const __half* qb = qkv + base + h * DHEAD;
    const __half* kb = qkv + base + DIMQ + h * DHEAD;
    const __half* vb = qkv + base + 2 * DIMQ + h * DHEAD;

    const float qscale = SCALE_A * LOG2E;

    const int cp_c  = tid & 7;
    const int cp_r0 = tid >> 3;

    auto issue_tile = [&](int kt, int s) {
        #pragma unroll
        for (int it = 0; it < 4; it++) {
            const int row = cp_r0 + 16 * it;
            const int pc  = cp_c ^ (row & 7);
            const uint32_t doff = (uint32_t)(row * 64 + pc * 8) * 2;
            cp16(ks_b[s] + doff, kb + (size_t)(kt + row) * QKV_N + cp_c * 8);
            cp16(vs_b[s] + doff, vb + (size_t)(kt + row) * QKV_N + cp_c * 8);
        }
        CP_COMMIT();
    };

    issue_tile(0, 0);
    issue_tile(64, 1);

    {
        const int row = tid;
        const __half* qrow = qb + (size_t)(q0 + row) * QKV_N;
        #pragma unroll
        for (int c = 0; c < 8; c++) {
            uint4 u = *(const uint4*)(qrow + c * 8);
            __half2* hp = (__half2*)&u;
            #pragma unroll
            for (int e = 0; e < 4; e++) {
                float2 f = __half22float2(hp[e]);
                hp[e] = __floats2half2_rn(f.x * qscale, f.y * qscale);
            }
            const int pc = c ^ (row & 7);
            *(uint4*)&QP[row * 64 + pc * 8] = u;
        }
    }
    __syncthreads();

    uint32_t qf[2][4][4];
    {
        const int x = lane & 7;
        #pragma unroll
        for (int mt = 0; mt < 2; mt++) {
            const int arow = wr + mt * 16 + (lane & 15);
            #pragma unroll
            for (int ks = 0; ks < 4; ks++) {
                const int pc = (2 * ks + (lane >> 4)) ^ x;
                ldsm_x4(qf[mt][ks], qp_b + (uint32_t)(arow * 64 + pc * 8) * 2);
            }
        }
    }

    float o[2][8][4];
    #pragma unroll
    for (int mt = 0; mt < 2; mt++)
        #pragma unroll
        for (int nt = 0; nt < 8; nt++)
            #pragma unroll
            for (int i = 0; i < 4; i++) o[mt][nt][i] = 0.f;
    float mi[2][2], li[2][2];
    #pragma unroll
    for (int mt = 0; mt < 2; mt++) {
        mi[mt][0] = -1e30f; mi[mt][1] = -1e30f;
        li[mt][0] = 0.f;    li[mt][1] = 0.f;
    }

    const int NT = SEQ / 64;
    int buf = 0;
    for (int t = 0; t < NT; t++) {
        if (t < NT - 1) CP_WAIT(1);   // tile t landed (t+1 may fly)
        else            CP_WAIT(0);   // tail-safe: last tile must land
        __syncthreads();

        if (t + 2 < NT)
            issue_tile((t + 2) * 64, (t + 2) % FA_STG);

        const uint32_t kbuf = ks_b[buf];
        const uint32_t vbuf = vs_b[buf];

        float s[2][8][4];
        #pragma unroll
        for (int mt = 0; mt < 2; mt++)
            #pragma unroll
            for (int nt = 0; nt < 8; nt++)
                #pragma unroll
                for (int i = 0; i < 4; i++) s[mt][nt][i] = 0.f;

        #pragma unroll
        for (int ks = 0; ks < 4; ks++) {
            uint32_t bf[8][2];
            #pragma unroll
            for (int bg = 0; bg < 4; bg++) {
                uint32_t t4[4];
                const int row = bg * 16 + (lane & 7) + ((lane >> 4) << 3);
                const int pc  = (2 * ks + ((lane >> 3) & 1)) ^ (lane & 7);
                ldsm_x4(t4, kbuf + (uint32_t)(row * 64 + pc * 8) * 2);
                bf[bg * 2][0]     = t4[0];
                bf[bg * 2][1]     = t4[1];
                bf[bg * 2 + 1][0] = t4[2];
                bf[bg * 2 + 1][1] = t4[3];
            }
            #pragma unroll
            for (int mt = 0; mt < 2; mt++)
                #pragma unroll
                for (int nt = 0; nt < 8; nt++)
                    mma_f16(s[mt][nt], qf[mt][ks], bf[nt]);
        }

        #pragma unroll
        for (int mt = 0; mt < 2; mt++) {
            float mlo = -1e30f, mhi = -1e30f;
            #pragma unroll
            for (int nt = 0; nt < 8; nt++) {
                mlo = fmaxf(mlo, fmaxf(s[mt][nt][0], s[mt][nt][1]));
                mhi = fmaxf(mhi, fmaxf(s[mt][nt][2], s[mt][nt][3]));
            }
            mlo = fmaxf(mlo, __shfl_xor_sync(0xffffffffu, mlo, 1));
            mlo = fmaxf(mlo, __shfl_xor_sync(0xffffffffu, mlo, 2));
            mhi = fmaxf(mhi, __shfl_xor_sync(0xffffffffu, mhi, 1));
            mhi = fmaxf(mhi, __shfl_xor_sync(0xffffffffu, mhi, 2));

            const float mn_lo = fmaxf(mi[mt][0], mlo);
            const float mn_hi = fmaxf(mi[mt][1], mhi);
            const float corr_lo = exp2f(mi[mt][0] - mn_lo);
            const float corr_hi = exp2f(mi[mt][1] - mn_hi);
            mi[mt][0] = mn_lo; mi[mt][1] = mn_hi;

            float rs_lo = 0.f, rs_hi = 0.f;
            #pragma unroll
            for (int nt = 0; nt < 8; nt++) {
                s[mt][nt][0] = exp2f(s[mt][nt][0] - mn_lo);
                s[mt][nt][1] = exp2f(s[mt][nt][1] - mn_lo);
                s[mt][nt][2] = exp2f(s[mt][nt][2] - mn_hi);
                s[mt][nt][3] = exp2f(s[mt][nt][3] - mn_hi);
                rs_lo += s[mt][nt][0] + s[mt][nt][1];
                rs_hi += s[mt][nt][2] + s[mt][nt][3];
            }
            rs_lo += __shfl_xor_sync(0xffffffffu, rs_lo, 1);
            rs_lo += __shfl_xor_sync(0xffffffffu, rs_lo, 2);
            rs_hi += __shfl_xor_sync(0xffffffffu, rs_hi, 1);
            rs_hi += __shfl_xor_sync(0xffffffffu, rs_hi, 2);

            li[mt][0] = li[mt][0] * corr_lo + rs_lo;
            li[mt][1] = li[mt][1] * corr_hi + rs_hi;

            #pragma unroll
            for (int nt = 0; nt < 8; nt++) {
                o[mt][nt][0] *= corr_lo; o[mt][nt][1] *= corr_lo;
                o[mt][nt][2] *= corr_hi; o[mt][nt][3] *= corr_hi;
            }
        }

        #pragma unroll
        for (int ks = 0; ks < 4; ks++) {
            uint32_t bfv[8][2];
            #pragma unroll
            for (int dt = 0; dt < 4; dt++) {
                uint32_t t4[4];
                const int row = ks * 16 + (lane & 7) + ((lane >> 4) << 3);
                const int pc  = (2 * dt + ((lane >> 3) & 1)) ^ (lane & 7);
                ldsm_x4_t(t4, vbuf + (uint32_t)(row * 64 + pc * 8) * 2);
                bfv[dt * 2][0]     = t4[0];
                bfv[dt * 2][1]     = t4[2];
                bfv[dt * 2 + 1][0] = t4[1];
                bfv[dt * 2 + 1][1] = t4[3];
            }
            #pragma unroll
            for (int mt = 0; mt < 2; mt++) {
                uint32_t ap[4];
                ap[0] = packh2(s[mt][2 * ks][0],     s[mt][2 * ks][1]);
                ap[1] = packh2(s[mt][2 * ks][2],     s[mt][2 * ks][3]);
                ap[2] = packh2(s[mt][2 * ks + 1][0], s[mt][2 * ks + 1][1]);
                ap[3] = packh2(s[mt][2 * ks + 1][2], s[mt][2 * ks + 1][3]);
                #pragma unroll
                for (int nt = 0; nt < 8; nt++)
                    mma_f16(o[mt][nt], ap, bfv[nt]);
            }
        }

        buf = (buf + 1) % FA_STG;
    }

    __half* ob = out + ((size_t)b * SEQ + q0) * DIMQ + h * DHEAD;
    #pragma unroll
    for (int mt = 0; mt < 2; mt++) {
        const float inv_lo = 1.f / li[mt][0];
        const float inv_hi = 1.f / li[mt][1];
        const int m = wr + mt * 16 + lq;
        #pragma unroll
        for (int nt = 0; nt < 8; nt++) {
            const int col = nt * 8 + 2 * lr;
            *(__half2*)(ob + (size_t)m * DIMQ + col) =
                __floats2half2_rn(o[mt][nt][0] * inv_lo, o[mt][nt][1] * inv_lo);
            *(__half2*)(ob + (size_t)(m + 8) * DIMQ + col) =
                __floats2half2_rn(o[mt][nt][2] * inv_hi, o[mt][nt][3] * inv_hi);
        }
    }
}

// ---------------------------------------------------------------------------
// Launch
// ---------------------------------------------------------------------------
extern "C" void kernel_launch(void* const* d_in, const int* in_sizes, int n_in,
                              void* d_out, int out_size)
{
    const float* x    = (const float*)d_in[0];   // [2,2048,1024]
    const float* Wqkv = (const float*)d_in[1];   // [1024,3072]
    const float* Wout = (const float*)d_in[2];   // [1024,1024]
    const float* bout = (const float*)d_in[3];   // [1024]
    float* out = (float*)d_out;                  // [2,2048,1024] f32

    __half *qkv, *att, *xh, *wqkvT, *woutT;
    cudaGetSymbolAddress((void**)&qkv, g_qkv);
    cudaGetSymbolAddress((void**)&att, g_att);
    cudaGetSymbolAddress((void**)&xh, g_xh);
    cudaGetSymbolAddress((void**)&wqkvT, g_wqkvT);
    cudaGetSymbolAddress((void**)&woutT, g_woutT);

    cudaFuncSetAttribute(gemm_f16,
                         cudaFuncAttributeMaxDynamicSharedMemorySize, GEMM_SMEM);
    cudaFuncSetAttribute(flash_attn_f16,
                         cudaFuncAttributeMaxDynamicSharedMemorySize, FA_SMEM);

    // Stage 0: convert x to fp16; convert+transpose weights to [n][k] fp16
    {
        int nx = NTOK * DIMQ;
        f32_to_f16<<<nx / 8 / 256, 256>>>(x, xh, nx);
        f32_to_f16_T<<<dim3(QKV_N / 32, DIMQ / 32), dim3(32, 8)>>>(
            Wqkv, wqkvT, DIMQ, QKV_N);
        f32_to_f16_T<<<dim3(DIMQ / 32, DIMQ / 32), dim3(32, 8)>>>(
            Wout, woutT, DIMQ, DIMQ);
    }

    // Stage 1: qkv = x @ W_qkv  (4096 x 3072 x 1024), fp16 out, persistent
    {
        int tiles = (NTOK / 128) * (QKV_N / 128);     // 768
        int grid = tiles < 2 * NSM ? tiles : 2 * NSM; // 296
        gemm_f16<<<grid, 128, GEMM_SMEM>>>(xh, wqkvT, nullptr, qkv,
                                           NTOK, QKV_N, DIMQ, 1);
    }

    // Stage 2: flash attention (128 q-rows per CTA, 4 warps), fp16 out
    {
        dim3 grid(SEQ / 128, HEADS, BATCH);
        flash_attn_f16<<<grid, 128, FA_SMEM>>>(qkv, att);
    }

    // Stage 3: out = att @ W_out + b_out  (4096 x 1024 x 1024), f32 out
    {
        int tiles = (NTOK / 128) * (DIMQ / 128);      // 256
        int grid = tiles < 2 * NSM ? tiles : 2 * NSM; // 256
        gemm_f16<<<grid, 128, GEMM_SMEM>>>(att, woutT, bout, out,
                                           NTOK, DIMQ, DIMQ, 0);
    }
}

// round 17
// speedup vs baseline: 1.0034x; 1.0034x over previous
#include <cuda_runtime.h>
#include <cuda_fp16.h>
#include <math.h>
#include <stdint.h>

#define DIMQ     1024
#define HEADS    16
#define DHEAD    64
#define SEQ      2048
#define BATCH    2
#define NTOK     (BATCH * SEQ)      // 4096
#define QKV_N    (3 * DIMQ)         // 3072
#define SCALE_A  0.125f             // 1/sqrt(64)
#define LOG2E    1.4426950408889634f
#define NSM      148

// Scratch (static device globals — allocation-free)
__device__ __half g_qkv[(size_t)NTOK * QKV_N];   // Q|K|V fp16
__device__ __half g_att[(size_t)NTOK * DIMQ];    // attention result fp16
__device__ __half g_xh[(size_t)NTOK * DIMQ];     // x fp16 [m][k]
__device__ __half g_wqkvT[(size_t)QKV_N * DIMQ]; // W_qkv^T fp16 [n][k]
__device__ __half g_woutT[(size_t)DIMQ * DIMQ];  // W_out^T fp16 [n][k]

// ---------------------------------------------------------------------------
// helpers
// ---------------------------------------------------------------------------
__device__ __forceinline__ uint32_t smem_u32(const void* p) {
    uint32_t a;
    asm("{ .reg .u64 t; cvta.to.shared.u64 t, %1; cvt.u32.u64 %0, t; }"
        : "=r"(a) : "l"(p));
    return a;
}
__device__ __forceinline__ void mma_f16(float* c, const uint32_t* a, const uint32_t* b) {
    asm volatile(
        "mma.sync.aligned.m16n8k16.row.col.f32.f16.f16.f32 "
        "{%0,%1,%2,%3},{%4,%5,%6,%7},{%8,%9},{%0,%1,%2,%3};"
        : "+f"(c[0]), "+f"(c[1]), "+f"(c[2]), "+f"(c[3])
        : "r"(a[0]), "r"(a[1]), "r"(a[2]), "r"(a[3]),
          "r"(b[0]), "r"(b[1]));
}
__device__ __forceinline__ void ldsm_x4(uint32_t* r, uint32_t addr) {
    asm volatile("ldmatrix.sync.aligned.m8n8.x4.shared.b16 {%0,%1,%2,%3}, [%4];"
                 : "=r"(r[0]), "=r"(r[1]), "=r"(r[2]), "=r"(r[3]) : "r"(addr));
}
__device__ __forceinline__ void ldsm_x4_t(uint32_t* r, uint32_t addr) {
    asm volatile("ldmatrix.sync.aligned.m8n8.x4.trans.shared.b16 {%0,%1,%2,%3}, [%4];"
                 : "=r"(r[0]), "=r"(r[1]), "=r"(r[2]), "=r"(r[3]) : "r"(addr));
}
__device__ __forceinline__ uint32_t packh2(float a, float b) {
    __half2 h = __floats2half2_rn(a, b);
    return *(uint32_t*)&h;
}
__device__ __forceinline__ void cp16(uint32_t dst, const void* src) {
    asm volatile("cp.async.cg.shared.global [%0], [%1], 16;"
                 :: "r"(dst), "l"(src) : "memory");
}
#define CP_COMMIT() asm volatile("cp.async.commit_group;" ::: "memory")
#define CP_WAIT(n)  asm volatile("cp.async.wait_group %0;" :: "n"(n) : "memory")

// ---------------------------------------------------------------------------
// f32 -> f16 convert (n multiple of 8)
// ---------------------------------------------------------------------------
__global__ void __launch_bounds__(256) f32_to_f16(
    const float* __restrict__ in, __half* __restrict__ out, int n)
{
    int i = (blockIdx.x * 256 + threadIdx.x) * 8;
    if (i < n) {
        float4 a = *(const float4*)(in + i);
        float4 b = *(const float4*)(in + i + 4);
        __half2 h[4];
        h[0] = __floats2half2_rn(a.x, a.y);
        h[1] = __floats2half2_rn(a.z, a.w);
        h[2] = __floats2half2_rn(b.x, b.y);
        h[3] = __floats2half2_rn(b.z, b.w);
        *(uint4*)(out + i) = *(uint4*)h;
    }
}

// f32 [R][C] -> f16 transposed [C][R]
__global__ void __launch_bounds__(256) f32_to_f16_T(
    const float* __restrict__ in, __half* __restrict__ out, int R, int C)
{
    __shared__ float t[32][33];
    int bx = blockIdx.x * 32, by = blockIdx.y * 32;
    int x = threadIdx.x, y = threadIdx.y;   // 32 x 8
    #pragma unroll
    for (int i = 0; i < 32; i += 8)
        t[y + i][x] = in[(size_t)(by + y + i) * C + bx + x];
    __syncthreads();
    #pragma unroll
    for (int i = 0; i < 32; i += 8)
        out[(size_t)(bx + y + i) * R + by + x] = __float2half(t[x][y + i]);
}

// ---------------------------------------------------------------------------
// fp16 mma.sync GEMM v6: persistent CTAs with CONTINUOUS cross-tile cp.async
// pipeline (no per-tile drain). 128x128 tile, BK=32, 4 warps (2x2), warp
// tile 64x64, 4-stage ring; stage of global chunk q = q & 3.
// ---------------------------------------------------------------------------
#define HST 40
#define NSTAGE 4
#define STG_HALVES (128 * HST)
#define GEMM_SMEM (2 * NSTAGE * STG_HALVES * 2)   // 81920 bytes

__global__ void __launch_bounds__(128, 2) gemm_f16(
    const __half* __restrict__ A, const __half* __restrict__ BT,
    const float* __restrict__ bias, void* __restrict__ Cout,
    int M, int N, int K, int out_half)
{
    extern __shared__ __half smh[];
    const uint32_t sb = smem_u32(smh);
    uint32_t as_b[NSTAGE], bs_b[NSTAGE];
    #pragma unroll
    for (int s = 0; s < NSTAGE; s++) {
        as_b[s] = sb + (uint32_t)(s * STG_HALVES) * 2;
        bs_b[s] = sb + (uint32_t)((NSTAGE + s) * STG_HALVES) * 2;
    }

    const int tid  = threadIdx.x;
    const int lane = tid & 31;
    const int wid  = tid >> 5;
    const int wm   = wid & 1;
    const int wn   = wid >> 1;

    const uint32_t sts_off = (uint32_t)(tid * HST) * 2;
    const uint32_t a_off = (uint32_t)((lane & 15) * HST + (lane >> 4) * 8) * 2;
    const uint32_t b_off = (uint32_t)(((lane & 7) + ((lane >> 4) << 3)) * HST
                                      + ((lane >> 3) & 1) * 8) * 2;
    const int lq = lane >> 2;
    const int lr = lane & 3;

    const int ntx = N / 128;
    const int ntiles = (M / 128) * ntx;
    const int NC = K / 32;
    const int G = gridDim.x;

    // ---- issue-side state (runs ahead over tile boundaries) ----
    int i_tile = blockIdx.x;
    int i_c = 0;
    const __half *IAp = A, *IBp = BT;
    if (i_tile < ntiles) {
        IAp = A  + (size_t)((long)(i_tile / ntx) * 128 + tid) * K;
        IBp = BT + (size_t)((long)(i_tile % ntx) * 128 + tid) * K;
    }
    long issued = 0;

    // issue one chunk into stage (issued & 3), advance issue state
    #define ISSUE_CHUNK() do {                                              \
        const int st = (int)(issued & (NSTAGE - 1));                        \
        const long kc = (long)i_c * 32;                                     \
        _Pragma("unroll")                                                   \
        for (int j = 0; j < 4; j++) {                                       \
            cp16(as_b[st] + sts_off + j * 16, IAp + kc + j * 8);            \
            cp16(bs_b[st] + sts_off + j * 16, IBp + kc + j * 8);            \
        }                                                                   \
        CP_COMMIT();                                                        \
        issued++;                                                           \
        if (++i_c == NC) {                                                  \
            i_c = 0;                                                        \
            i_tile += G;                                                    \
            if (i_tile < ntiles) {                                          \
                IAp = A  + (size_t)((long)(i_tile / ntx) * 128 + tid) * K;  \
                IBp = BT + (size_t)((long)(i_tile % ntx) * 128 + tid) * K;  \
            }                                                               \
        }                                                                   \
    } while (0)

    // prologue: up to 3 chunks
    #pragma unroll
    for (int s = 0; s < 3; s++)
        if (i_tile < ntiles) ISSUE_CHUNK();

    // ---- compute side ----
    long q = 0;
    for (int c_tile = blockIdx.x; c_tile < ntiles; c_tile += G) {
        const long row0 = (long)(c_tile / ntx) * 128;
        const long col0 = (long)(c_tile % ntx) * 128;

        float acc[4][8][4];
        #pragma unroll
        for (int mt = 0; mt < 4; mt++)
            #pragma unroll
            for (int nt = 0; nt < 8; nt++)
                #pragma unroll
                for (int i = 0; i < 4; i++) acc[mt][nt][i] = 0.f;

        for (int c = 0; c < NC; c++) {
            // wait until chunk q has landed
            const long ahead = issued - q - 1;
            if (ahead >= 2)      CP_WAIT(2);
            else if (ahead == 1) CP_WAIT(1);
            else                 CP_WAIT(0);
            __syncthreads();

            if (i_tile < ntiles) ISSUE_CHUNK();

            const int buf = (int)(q & (NSTAGE - 1));
            #pragma unroll
            for (int ks = 0; ks < 2; ks++) {
                uint32_t af[4][4];
                #pragma unroll
                for (int mt = 0; mt < 4; mt++)
                    ldsm_x4(af[mt], as_b[buf]
                            + (uint32_t)((wm * 64 + mt * 16) * HST + ks * 16) * 2
                            + a_off);
                uint32_t bf[8][2];
                #pragma unroll
                for (int bg = 0; bg < 4; bg++) {
                    uint32_t t[4];
                    ldsm_x4(t, bs_b[buf]
                            + (uint32_t)((wn * 64 + bg * 16) * HST + ks * 16) * 2
                            + b_off);
                    bf[bg * 2][0]     = t[0];
                    bf[bg * 2][1]     = t[1];
                    bf[bg * 2 + 1][0] = t[2];
                    bf[bg * 2 + 1][1] = t[3];
                }
                #pragma unroll
                for (int mt = 0; mt < 4; mt++)
                    #pragma unroll
                    for (int nt = 0; nt < 8; nt++)
                        mma_f16(acc[mt][nt], af[mt], bf[nt]);
            }
            q++;
        }

        // epilogue (regs -> gmem; no smem: overlaps in-flight copies)
        if (out_half) {
            __half* Ch = (__half*)Cout;
            #pragma unroll
            for (int mt = 0; mt < 4; mt++) {
                long r0 = row0 + wm * 64 + mt * 16 + lq;
                #pragma unroll
                for (int nt = 0; nt < 8; nt++) {
                    long c = col0 + wn * 64 + nt * 8 + 2 * lr;
                    *(__half2*)(Ch + r0 * N + c) =
                        __floats2half2_rn(acc[mt][nt][0], acc[mt][nt][1]);
                    *(__half2*)(Ch + (r0 + 8) * N + c) =
                        __floats2half2_rn(acc[mt][nt][2], acc[mt][nt][3]);
                }
            }
        } else {
            float* Cf = (float*)Cout;
            #pragma unroll
            for (int mt = 0; mt < 4; mt++) {
                long r0 = row0 + wm * 64 + mt * 16 + lq;
                #pragma unroll
                for (int nt = 0; nt < 8; nt++) {
                    long c = col0 + wn * 64 + nt * 8 + 2 * lr;
                    float bx = bias ? bias[c] : 0.f;
                    float by = bias ? bias[c + 1] : 0.f;
                    float2 v0, v1;
                    v0.x = acc[mt][nt][0] + bx; v0.y = acc[mt][nt][1] + by;
                    v1.x = acc[mt][nt][2] + bx; v1.y = acc[mt][nt][3] + by;
                    *(float2*)(Cf + r0 * N + c)       = v0;
                    *(float2*)(Cf + (r0 + 8) * N + c) = v1;
                }
            }
        }
    }
    #undef ISSUE_CHUNK
}

// ---------------------------------------------------------------------------
// fp16 flash attention v4 (R16 version: tail-safe waits). CTA = 128 q-rows,
// 4 warps, register-direct P, 3-stage cp.async K/V pipeline.
// ---------------------------------------------------------------------------
#define FA_STG 3
#define FA_SMEM ((8192 + 6 * 4096) * 2)   // 65536 bytes

__global__ void __launch_bounds__(128, 2) flash_attn_f16(
    const __half* __restrict__ qkv, __half* __restrict__ out)
{
    extern __shared__ __half fsm[];
    const uint32_t sb = smem_u32(fsm);
    const uint32_t qp_b = sb;
    uint32_t ks_b[FA_STG], vs_b[FA_STG];
    #pragma unroll
    for (int s = 0; s < FA_STG; s++) {
        ks_b[s] = sb + (uint32_t)(8192 + s * 4096) * 2;
        vs_b[s] = sb + (uint32_t)(8192 + (3 + s) * 4096) * 2;
    }
    __half* QP = fsm;

    const int tid  = threadIdx.x;
    const int lane = tid & 31;
    const int wid  = tid >> 5;
    const int lq   = lane >> 2;
    const int lr   = lane & 3;
    const int wr   = wid * 32;

    const int h  = blockIdx.y;
    const int b  = blockIdx.z;
    const int q0 = blockIdx.x * 128;

    const size_t base = (size_t)b * SEQ * QKV_N;
    const __half* qb = qkv + base + h * DHEAD;
    const __half* kb = qkv + base + DIMQ + h * DHEAD;
    const __half* vb = qkv + base + 2 * DIMQ + h * DHEAD;

    const float qscale = SCALE_A * LOG2E;

    const int cp_c  = tid & 7;
    const int cp_r0 = tid >> 3;

    auto issue_tile = [&](int kt, int s) {
        #pragma unroll
        for (int it = 0; it < 4; it++) {
            const int row = cp_r0 + 16 * it;
            const int pc  = cp_c ^ (row & 7);
            const uint32_t doff = (uint32_t)(row * 64 + pc * 8) * 2;
            cp16(ks_b[s] + doff, kb + (size_t)(kt + row) * QKV_N + cp_c * 8);
            cp16(vs_b[s] + doff, vb + (size_t)(kt + row) * QKV_N + cp_c * 8);
        }
        CP_COMMIT();
    };

    issue_tile(0, 0);
    issue_tile(64, 1);

    {
        const int row = tid;
        const __half* qrow = qb + (size_t)(q0 + row) * QKV_N;
        #pragma unroll
        for (int c = 0; c < 8; c++) {
            uint4 u = *(const uint4*)(qrow + c * 8);
            __half2* hp = (__half2*)&u;
            #pragma unroll
            for (int e = 0; e < 4; e++) {
                float2 f = __half22float2(hp[e]);
                hp[e] = __floats2half2_rn(f.x * qscale, f.y * qscale);
            }
            const int pc = c ^ (row & 7);
            *(uint4*)&QP[row * 64 + pc * 8] = u;
        }
    }
    __syncthreads();

    uint32_t qf[2][4][4];
    {
        const int x = lane & 7;
        #pragma unroll
        for (int mt = 0; mt < 2; mt++) {
            const int arow = wr + mt * 16 + (lane & 15);
            #pragma unroll
            for (int ks = 0; ks < 4; ks++) {
                const int pc = (2 * ks + (lane >> 4)) ^ x;
                ldsm_x4(qf[mt][ks], qp_b + (uint32_t)(arow * 64 + pc * 8) * 2);
            }
        }
    }

    float o[2][8][4];
    #pragma unroll
    for (int mt = 0; mt < 2; mt++)
        #pragma unroll
        for (int nt = 0; nt < 8; nt++)
            #pragma unroll
            for (int i = 0; i < 4; i++) o[mt][nt][i] = 0.f;
    float mi[2][2], li[2][2];
    #pragma unroll
    for (int mt = 0; mt < 2; mt++) {
        mi[mt][0] = -1e30f; mi[mt][1] = -1e30f;
        li[mt][0] = 0.f;    li[mt][1] = 0.f;
    }

    const int NT = SEQ / 64;
    int buf = 0;
    for (int t = 0; t < NT; t++) {
        if (t < NT - 1) CP_WAIT(1);
        else            CP_WAIT(0);
        __syncthreads();

        if (t + 2 < NT)
            issue_tile((t + 2) * 64, (t + 2) % FA_STG);

        const uint32_t kbuf = ks_b[buf];
        const uint32_t vbuf = vs_b[buf];

        float s[2][8][4];
        #pragma unroll
        for (int mt = 0; mt < 2; mt++)
            #pragma unroll
            for (int nt = 0; nt < 8; nt++)
                #pragma unroll
                for (int i = 0; i < 4; i++) s[mt][nt][i] = 0.f;

        #pragma unroll
        for (int ks = 0; ks < 4; ks++) {
            uint32_t bf[8][2];
            #pragma unroll
            for (int bg = 0; bg < 4; bg++) {
                uint32_t t4[4];
                const int row = bg * 16 + (lane & 7) + ((lane >> 4) << 3);
                const int pc  = (2 * ks + ((lane >> 3) & 1)) ^ (lane & 7);
                ldsm_x4(t4, kbuf + (uint32_t)(row * 64 + pc * 8) * 2);
                bf[bg * 2][0]     = t4[0];
                bf[bg * 2][1]     = t4[1];
                bf[bg * 2 + 1][0] = t4[2];
                bf[bg * 2 + 1][1] = t4[3];
            }
            #pragma unroll
            for (int mt = 0; mt < 2; mt++)
                #pragma unroll
                for (int nt = 0; nt < 8; nt++)
                    mma_f16(s[mt][nt], qf[mt][ks], bf[nt]);
        }

        #pragma unroll
        for (int mt = 0; mt < 2; mt++) {
            float mlo = -1e30f, mhi = -1e30f;
            #pragma unroll
            for (int nt = 0; nt < 8; nt++) {
                mlo = fmaxf(mlo, fmaxf(s[mt][nt][0], s[mt][nt][1]));
                mhi = fmaxf(mhi, fmaxf(s[mt][nt][2], s[mt][nt][3]));
            }
            mlo = fmaxf(mlo, __shfl_xor_sync(0xffffffffu, mlo, 1));
            mlo = fmaxf(mlo, __shfl_xor_sync(0xffffffffu, mlo, 2));
            mhi = fmaxf(mhi, __shfl_xor_sync(0xffffffffu, mhi, 1));
            mhi = fmaxf(mhi, __shfl_xor_sync(0xffffffffu, mhi, 2));

            const float mn_lo = fmaxf(mi[mt][0], mlo);
            const float mn_hi = fmaxf(mi[mt][1], mhi);
            const float corr_lo = exp2f(mi[mt][0] - mn_lo);
            const float corr_hi = exp2f(mi[mt][1] - mn_hi);
            mi[mt][0] = mn_lo; mi[mt][1] = mn_hi;

            float rs_lo = 0.f, rs_hi = 0.f;
            #pragma unroll
            for (int nt = 0; nt < 8; nt++) {
                s[mt][nt][0] = exp2f(s[mt][nt][0] - mn_lo);
                s[mt][nt][1] = exp2f(s[mt][nt][1] - mn_lo);
                s[mt][nt][2] = exp2f(s[mt][nt][2] - mn_hi);
                s[mt][nt][3] = exp2f(s[mt][nt][3] - mn_hi);
                rs_lo += s[mt][nt][0] + s[mt][nt][1];
                rs_hi += s[mt][nt][2] + s[mt][nt][3];
            }
            rs_lo += __shfl_xor_sync(0xffffffffu, rs_lo, 1);
            rs_lo += __shfl_xor_sync(0xffffffffu, rs_lo, 2);
            rs_hi += __shfl_xor_sync(0xffffffffu, rs_hi, 1);
            rs_hi += __shfl_xor_sync(0xffffffffu, rs_hi, 2);

            li[mt][0] = li[mt][0] * corr_lo + rs_lo;
            li[mt][1] = li[mt][1] * corr_hi + rs_hi;

            #pragma unroll
            for (int nt = 0; nt < 8; nt++) {
                o[mt][nt][0] *= corr_lo; o[mt][nt][1] *= corr_lo;
                o[mt][nt][2] *= corr_hi; o[mt][nt][3] *= corr_hi;
            }
        }

        #pragma unroll
        for (int ks = 0; ks < 4; ks++) {
            uint32_t bfv[8][2];
            #pragma unroll
            for (int dt = 0; dt < 4; dt++) {
                uint32_t t4[4];
                const int row = ks * 16 + (lane & 7) + ((lane >> 4) << 3);
                const int pc  = (2 * dt + ((lane >> 3) & 1)) ^ (lane & 7);
                ldsm_x4_t(t4, vbuf + (uint32_t)(row * 64 + pc * 8) * 2);
                bfv[dt * 2][0]     = t4[0];
                bfv[dt * 2][1]     = t4[2];
                bfv[dt * 2 + 1][0] = t4[1];
                bfv[dt * 2 + 1][1] = t4[3];
            }
            #pragma unroll
            for (int mt = 0; mt < 2; mt++) {
                uint32_t ap[4];
                ap[0] = packh2(s[mt][2 * ks][0],     s[mt][2 * ks][1]);
                ap[1] = packh2(s[mt][2 * ks][2],     s[mt][2 * ks][3]);
                ap[2] = packh2(s[mt][2 * ks + 1][0], s[mt][2 * ks + 1][1]);
                ap[3] = packh2(s[mt][2 * ks + 1][2], s[mt][2 * ks + 1][3]);
                #pragma unroll
                for (int nt = 0; nt < 8; nt++)
                    mma_f16(o[mt][nt], ap, bfv[nt]);
            }
        }

        buf = (buf + 1) % FA_STG;
    }

    __half* ob = out + ((size_t)b * SEQ + q0) * DIMQ + h * DHEAD;
    #pragma unroll
    for (int mt = 0; mt < 2; mt++) {
        const float inv_lo = 1.f / li[mt][0];
        const float inv_hi = 1.f / li[mt][1];
        const int m = wr + mt * 16 + lq;
        #pragma unroll
        for (int nt = 0; nt < 8; nt++) {
            const int col = nt * 8 + 2 * lr;
            *(__half2*)(ob + (size_t)m * DIMQ + col) =
                __floats2half2_rn(o[mt][nt][0] * inv_lo, o[mt][nt][1] * inv_lo);
            *(__half2*)(ob + (size_t)(m + 8) * DIMQ + col) =
                __floats2half2_rn(o[mt][nt][2] * inv_hi, o[mt][nt][3] * inv_hi);
        }
    }
}

// ---------------------------------------------------------------------------
// Launch
// ---------------------------------------------------------------------------
extern "C" void kernel_launch(void* const* d_in, const int* in_sizes, int n_in,
                              void* d_out, int out_size)
{
    const float* x    = (const float*)d_in[0];   // [2,2048,1024]
    const float* Wqkv = (const float*)d_in[1];   // [1024,3072]
    const float* Wout = (const float*)d_in[2];   // [1024,1024]
    const float* bout = (const float*)d_in[3];   // [1024]
    float* out = (float*)d_out;                  // [2,2048,1024] f32

    __half *qkv, *att, *xh, *wqkvT, *woutT;
    cudaGetSymbolAddress((void**)&qkv, g_qkv);
    cudaGetSymbolAddress((void**)&att, g_att);
    cudaGetSymbolAddress((void**)&xh, g_xh);
    cudaGetSymbolAddress((void**)&wqkvT, g_wqkvT);
    cudaGetSymbolAddress((void**)&woutT, g_woutT);

    cudaFuncSetAttribute(gemm_f16,
                         cudaFuncAttributeMaxDynamicSharedMemorySize, GEMM_SMEM);
    cudaFuncSetAttribute(flash_attn_f16,
                         cudaFuncAttributeMaxDynamicSharedMemorySize, FA_SMEM);

    // Stage 0: convert x to fp16; convert+transpose weights to [n][k] fp16
    {
        int nx = NTOK * DIMQ;
        f32_to_f16<<<nx / 8 / 256, 256>>>(x, xh, nx);
        f32_to_f16_T<<<dim3(QKV_N / 32, DIMQ / 32), dim3(32, 8)>>>(
            Wqkv, wqkvT, DIMQ, QKV_N);
        f32_to_f16_T<<<dim3(DIMQ / 32, DIMQ / 32), dim3(32, 8)>>>(
            Wout, woutT, DIMQ, DIMQ);
    }

    // Stage 1: qkv = x @ W_qkv  (4096 x 3072 x 1024), fp16 out, persistent
    {
        int tiles = (NTOK / 128) * (QKV_N / 128);     // 768
        int grid = tiles < 2 * NSM ? tiles : 2 * NSM; // 296
        gemm_f16<<<grid, 128, GEMM_SMEM>>>(xh, wqkvT, nullptr, qkv,
                                           NTOK, QKV_N, DIMQ, 1);
    }

    // Stage 2: flash attention (128 q-rows per CTA, 4 warps), fp16 out
    {
        dim3 grid(SEQ / 128, HEADS, BATCH);
        flash_attn_f16<<<grid, 128, FA_SMEM>>>(qkv, att);
    }

    // Stage 3: out = att @ W_out + b_out  (4096 x 1024 x 1024), f32 out
    {
        int tiles = (NTOK / 128) * (DIMQ / 128);      // 256
        int grid = tiles < 2 * NSM ? tiles : 2 * NSM; // 256
        gemm_f16<<<grid, 128, GEMM_SMEM>>>(att, woutT, bout, out,
                                           NTOK, DIMQ, DIMQ, 0);
    }
}